// round 16
// baseline (speedup 1.0000x reference)
#include <cuda_runtime.h>
#include <cuda_fp16.h>
#include <stdint.h>

#define SEQ   2048
#define DM    1024
#define NH    16
#define HD    64
#define BATCH 4
#define MT    (BATCH * SEQ)   // 8192

// ---------------------------------------------------------------------------
// Scratch (static device globals — no allocations allowed)
// ---------------------------------------------------------------------------
__device__ __half g_xh[(size_t)MT * DM];
__device__ __half g_wqh[(size_t)DM * DM];
__device__ __half g_wkh[(size_t)DM * DM];
__device__ __half g_wvh[(size_t)DM * DM];
__device__ __half g_woh[(size_t)DM * DM];
__device__ __half g_qh[(size_t)MT * DM];     // [B,H,S,Dh]
__device__ __half g_kh[(size_t)MT * DM];     // [B,H,S,Dh]
__device__ __half g_vh[(size_t)MT * DM];     // [B,H,S,Dh]
__device__ __half g_ch[(size_t)MT * DM];     // context [M,D] (fp16)

// ---------------------------------------------------------------------------
// PTX helpers
// ---------------------------------------------------------------------------
__device__ __forceinline__ uint32_t sptr(const void* p) {
    return (uint32_t)__cvta_generic_to_shared(p);
}
__device__ __forceinline__ void ldsm_x4(uint32_t* r, uint32_t a) {
    asm volatile("ldmatrix.sync.aligned.m8n8.x4.shared.b16 {%0,%1,%2,%3}, [%4];"
                 : "=r"(r[0]), "=r"(r[1]), "=r"(r[2]), "=r"(r[3]) : "r"(a));
}
__device__ __forceinline__ void ldsm_x4t(uint32_t* r, uint32_t a) {
    asm volatile("ldmatrix.sync.aligned.m8n8.x4.trans.shared.b16 {%0,%1,%2,%3}, [%4];"
                 : "=r"(r[0]), "=r"(r[1]), "=r"(r[2]), "=r"(r[3]) : "r"(a));
}
__device__ __forceinline__ void mma_f16(float* c, const uint32_t* a, const uint32_t* b) {
    asm volatile(
        "mma.sync.aligned.m16n8k16.row.col.f32.f16.f16.f32 "
        "{%0,%1,%2,%3}, {%4,%5,%6,%7}, {%8,%9}, {%0,%1,%2,%3};"
        : "+f"(c[0]), "+f"(c[1]), "+f"(c[2]), "+f"(c[3])
        : "r"(a[0]), "r"(a[1]), "r"(a[2]), "r"(a[3]), "r"(b[0]), "r"(b[1]));
}
__device__ __forceinline__ void cpa16(uint32_t s, const void* g) {
    asm volatile("cp.async.cg.shared.global [%0], [%1], 16;" :: "r"(s), "l"(g));
}
#define CPA_COMMIT asm volatile("cp.async.commit_group;" ::: "memory")
#define CPA_WAIT2  asm volatile("cp.async.wait_group 2;" ::: "memory")
#define CPA_WAIT1  asm volatile("cp.async.wait_group 1;" ::: "memory")
#define CPA_WAIT0  asm volatile("cp.async.wait_group 0;" ::: "memory")

__device__ __forceinline__ float fexp2(float x) {
    float r;
    asm("ex2.approx.f32 %0, %1;" : "=f"(r) : "f"(x));
    return r;
}
__device__ __forceinline__ uint32_t packh2(float v0, float v1) {
    __half2 h = __floats2half2_rn(v0, v1);
    return *(uint32_t*)&h;
}

// ---------------------------------------------------------------------------
// Fused convert kernel: x and all 4 weights -> fp16. (unchanged)
// ---------------------------------------------------------------------------
#define NX4  (MT * DM / 4)     // 2,097,152
#define NW4  (DM * DM / 4)     //   262,144
#define NTOT (NX4 + 4 * NW4)   // 3,145,728
#define NTHR (NTOT / 4)        //   786,432 threads, 4 slots each

__global__ __launch_bounds__(256) void split_all(
    const float4* __restrict__ x,  const float4* __restrict__ wq,
    const float4* __restrict__ wk, const float4* __restrict__ wv,
    const float4* __restrict__ wo)
{
    const int t = blockIdx.x * 256 + threadIdx.x;
#pragma unroll
    for (int k = 0; k < 4; k++) {
        const int i = t + k * NTHR;
        const float4* src;
        __half* H;
        int j;
        if (i < NX4) {
            src = x; H = g_xh; j = i;
        } else {
            j = i - NX4;
            const int which = j / NW4;
            j -= which * NW4;
            src = (which == 0) ? wq : (which == 1) ? wk : (which == 2) ? wv : wo;
            H   = (which == 0) ? g_wqh : (which == 1) ? g_wkh
                : (which == 2) ? g_wvh : g_woh;
        }
        float4 v = src[j];
        ((__half2*)(H + (size_t)j * 4))[0] = __floats2half2_rn(v.x, v.y);
        ((__half2*)(H + (size_t)j * 4))[1] = __floats2half2_rn(v.z, v.w);
    }
}

// ---------------------------------------------------------------------------
// Single-term fp16 GEMM, occupancy-3 variant:
// Block tile 64(m) x 128(n), 256 threads, warp grid 2x4, warp tile 32x32.
// C accum = 32 regs/thread -> fits 3 CTAs/SM (24 warps).
// k-chunk 64, 2-stage cp.async ring.
// MODE 0 (QKV, z selects weight): A=x, fp16 out to [B,H,S,Dh]
// MODE 1 (Oproj): A=context, B=Wo, fp32 out
// ---------------------------------------------------------------------------
#define HP 72                        // smem pitch (halves)
#define HT_A (64 * HP * 2)           //  9216 bytes (A tile: 64 rows)
#define HT_B (128 * HP * 2)          // 18432 bytes (B tile: 128 rows)
#define GSTAGE_B (HT_A + HT_B)       // 27648
#define GSMEM    (2 * GSTAGE_B)      // 55296 (x3 CTAs = 165888 <= 227KB)

template <int MODE>
__global__ __launch_bounds__(256, 3) void hgemm(const float* b0, const float* b1,
                                                const float* b2, float* outf)
{
    extern __shared__ char smg[];
    const uint32_t su = sptr(smg);

    const int tid = threadIdx.x, wid = tid >> 5, lane = tid & 31;
    const int n0 = blockIdx.x * 128;
    const int m0 = blockIdx.y * 64;
    const int wm = (wid & 1) * 32;          // warp m offset (2 warps in m)
    const int wn = (wid >> 1) * 32;         // warp n offset (4 warps in n)

    const __half *gAh, *gBh;
    __half *Oh = nullptr;
    const float* bias;
    if (MODE == 0) {
        gAh = g_xh;
        const int which = blockIdx.z;
        if      (which == 0) { gBh = g_wqh; bias = b0; Oh = g_qh; }
        else if (which == 1) { gBh = g_wkh; bias = b1; Oh = g_kh; }
        else                 { gBh = g_wvh; bias = b2; Oh = g_vh; }
    } else {
        gAh = g_ch; gBh = g_woh; bias = b0;
    }

    float C[2][4][4];                        // 32 regs
#pragma unroll
    for (int a = 0; a < 2; a++)
#pragma unroll
        for (int b = 0; b < 4; b++)
#pragma unroll
            for (int c = 0; c < 4; c++) C[a][b][c] = 0.0f;

    // stage load: A = 64x64 halves (512 float4, 2/thread);
    //             B = 128x64 halves (1024 float4, 4/thread)
    auto load_stage = [&](int s, int k0) {
        const uint32_t sb = su + s * GSTAGE_B;
#pragma unroll
        for (int i = 0; i < 2; i++) {
            const int slot = i * 256 + tid;
            const int r = slot >> 3, c = (slot & 7) * 8;
            cpa16(sb + r * (HP * 2) + c * 2,
                  gAh + (size_t)(m0 + r) * DM + k0 + c);
        }
#pragma unroll
        for (int i = 0; i < 4; i++) {
            const int slot = i * 256 + tid;
            const int r = slot >> 3, c = (slot & 7) * 8;
            cpa16(sb + HT_A + r * (HP * 2) + c * 2,
                  gBh + (size_t)(n0 + r) * DM + k0 + c);
        }
    };

    load_stage(0, 0);
    CPA_COMMIT;

    const int a_row0 = wm + (lane & 15);
    const int a_colb = 8 * (lane >> 4);
    const int b_row0 = wn + (lane & 7) + 8 * (lane >= 16);
    const int b_colb = 8 * ((lane >> 3) & 1);

    for (int it = 0; it < 16; it++) {
        const int s = it & 1;
        if (it + 1 < 16) {
            load_stage(s ^ 1, (it + 1) * 64);
            CPA_COMMIT;
            CPA_WAIT1;
        } else {
            CPA_WAIT0;
        }
        __syncthreads();

        const __half* sAh = (const __half*)(smg + s * GSTAGE_B);
        const __half* sBh = (const __half*)(smg + s * GSTAGE_B + HT_A);

#pragma unroll
        for (int ks = 0; ks < 4; ks++) {
            const int kk = ks * 16;
            uint32_t ah[2][4], bh[2][4];
#pragma unroll
            for (int mt = 0; mt < 2; mt++)
                ldsm_x4(ah[mt], sptr(&sAh[(a_row0 + mt * 16) * HP + kk + a_colb]));
#pragma unroll
            for (int nq = 0; nq < 2; nq++)
                ldsm_x4(bh[nq], sptr(&sBh[(b_row0 + nq * 16) * HP + kk + b_colb]));
#pragma unroll
            for (int nq = 0; nq < 2; nq++) {
                mma_f16(C[0][nq * 2],     ah[0], bh[nq]);
                mma_f16(C[0][nq * 2 + 1], ah[0], bh[nq] + 2);
                mma_f16(C[1][nq * 2],     ah[1], bh[nq]);
                mma_f16(C[1][nq * 2 + 1], ah[1], bh[nq] + 2);
            }
        }
        __syncthreads();
    }

#pragma unroll
    for (int mt = 0; mt < 2; mt++)
#pragma unroll
        for (int nt = 0; nt < 4; nt++)
#pragma unroll
            for (int half = 0; half < 2; half++) {
                const int r = m0 + wm + mt * 16 + (lane >> 2) + half * 8;
                const int c = n0 + wn + nt * 8 + (lane & 3) * 2;
                const float v0 = C[mt][nt][half * 2 + 0] + __ldg(&bias[c]);
                const float v1 = C[mt][nt][half * 2 + 1] + __ldg(&bias[c + 1]);
                if (MODE == 0) {
                    const int b = r >> 11, s = r & 2047, h = c >> 6, d = c & 63;
                    const size_t off = ((((size_t)(b * NH + h)) * SEQ + s) << 6) + d;
                    *(__half2*)&Oh[off] = __floats2half2_rn(v0, v1);
                } else {
                    *(float2*)&outf[(size_t)r * DM + c] = make_float2(v0, v1);
                }
            }
}

// ---------------------------------------------------------------------------
// Flash attention (unchanged from R14): single-term fp16 mma, register-P,
// fp32 softmax with folded scale + ones-mma row sums, 4-stage cp.async KV,
// one sync/iter, Q via cp.async.
// ---------------------------------------------------------------------------
#define AP 72
#define AQ_T      (128 * AP * 2)          // 18432 (Qh)
#define AKV_T     (64 * AP * 2)           // 9216
#define AKV_STAGE (2 * AKV_T)             // 18432 (Kh, Vh)
#define A_KV0     AQ_T                    // 18432
#define ASMEM     (A_KV0 + 4 * AKV_STAGE) // 92160  (x2 CTAs = 184320 <= 227KB)

__global__ __launch_bounds__(256, 2) void attn_kernel()
{
    extern __shared__ char sma[];
    const uint32_t su = sptr(sma);
    __half* Qh = (__half*)sma;

    const int tid = threadIdx.x, wid = tid >> 5, lane = tid & 31;
    const int bh = blockIdx.y;
    const int q0 = blockIdx.x * 128;
    const size_t base = (size_t)bh * SEQ * HD;

    const int kr = tid >> 3;            // 0..31
    const int kc = (tid & 7) * 8;

    auto load_kv = [&](int s, int s0) {
        const uint32_t sb = su + A_KV0 + s * AKV_STAGE;
#pragma unroll
        for (int i = 0; i < 2; i++) {
            const int r = kr + i * 32;
            const size_t g = base + (size_t)(s0 + r) * HD + kc;
            const uint32_t so = r * (AP * 2) + kc * 2;
            cpa16(sb + so,           g_kh + g);
            cpa16(sb + AKV_T + so,   g_vh + g);
        }
    };

    // Q tile (128x64) via cp.async, grouped with KV stage 0
#pragma unroll
    for (int i = 0; i < 4; i++) {
        const int slot = i * 256 + tid;
        const int r = slot >> 3, c = (slot & 7) * 8;
        cpa16(su + r * (AP * 2) + c * 2,
              g_qh + base + (size_t)(q0 + r) * HD + c);
    }
    load_kv(0, 0);
    CPA_COMMIT;
    load_kv(1, 64);
    CPA_COMMIT;
    load_kv(2, 128);
    CPA_COMMIT;

    // wait for Q + stage 0 (2 groups still in flight), then hoist Q frags
    CPA_WAIT2;
    __syncthreads();

    uint32_t qh_f[4][4];
#pragma unroll
    for (int kt = 0; kt < 4; kt++) {
        const int row = wid * 16 + (lane & 15);
        const int col = kt * 16 + 8 * (lane >> 4);
        ldsm_x4(qh_f[kt], sptr(&Qh[row * AP + col]));
    }

    float m_i[2] = {-1e30f, -1e30f}, l_i[2] = {0.0f, 0.0f};
    float O[8][4];
#pragma unroll
    for (int a = 0; a < 8; a++)
#pragma unroll
        for (int b = 0; b < 4; b++) O[a][b] = 0.0f;

    const float SCALE = 0.125f * 1.44269504089f;   // 1/sqrt(64) * log2(e)
    const uint32_t ONES2 = 0x3C003C00u;            // half2 {1, 1}
    const uint32_t onesb[2] = {ONES2, ONES2};
    const int NIT = SEQ / 64;                      // 32

    for (int it = 0; it < NIT; it++) {
        const int s = it & 3;
        if (it > 0) {
            if (it < NIT - 1) { CPA_WAIT2; } else { CPA_WAIT0; }
            __syncthreads();           // stage s ready; stage (it+3)&3 free
        }
        if (it + 3 < NIT) {
            load_kv((it + 3) & 3, (it + 3) * 64);
            CPA_COMMIT;
        }

        const __half* Kh = (const __half*)(sma + A_KV0 + s * AKV_STAGE);
        const __half* Vh = (const __half*)(sma + A_KV0 + s * AKV_STAGE + AKV_T);

        // ---- S = Q K^T (single term) ----
        float S[8][4];
#pragma unroll
        for (int a = 0; a < 8; a++)
#pragma unroll
            for (int b = 0; b < 4; b++) S[a][b] = 0.0f;

#pragma unroll
        for (int kt = 0; kt < 4; kt++) {
#pragma unroll
            for (int np = 0; np < 4; np++) {
                const int row = np * 16 + (lane & 7) + 8 * (lane >= 16);
                const int col = kt * 16 + 8 * ((lane >> 3) & 1);
                uint32_t kh_f[4];
                ldsm_x4(kh_f, sptr(&Kh[row * AP + col]));
                mma_f16(S[np * 2],     qh_f[kt], kh_f);
                mma_f16(S[np * 2 + 1], qh_f[kt], kh_f + 2);
            }
        }

        // ---- online softmax: raw-unit max, scale folded into exp FFMA ----
        float alpha_s[2];
#pragma unroll
        for (int i = 0; i < 2; i++) {
            float rowmax = -1e30f;
#pragma unroll
            for (int nt = 0; nt < 8; nt++)
                rowmax = fmaxf(rowmax, fmaxf(S[nt][2 * i], S[nt][2 * i + 1]));
            rowmax = fmaxf(rowmax, __shfl_xor_sync(0xffffffffu, rowmax, 1));
            rowmax = fmaxf(rowmax, __shfl_xor_sync(0xffffffffu, rowmax, 2));
            const float mnew  = fmaxf(m_i[i], rowmax);
            const float alpha = fexp2((m_i[i] - mnew) * SCALE);
            alpha_s[i] = alpha;
            m_i[i] = mnew;
            const float nms = -mnew * SCALE;
#pragma unroll
            for (int nt = 0; nt < 8; nt++) {
                S[nt][2 * i]     = fexp2(fmaf(S[nt][2 * i],     SCALE, nms));
                S[nt][2 * i + 1] = fexp2(fmaf(S[nt][2 * i + 1], SCALE, nms));
                O[nt][2 * i]     *= alpha;
                O[nt][2 * i + 1] *= alpha;
            }
        }

        // ---- pack P fragments from S registers (C-layout == A-layout) ----
        uint32_t pf[4][4];
#pragma unroll
        for (int kt = 0; kt < 4; kt++) {
            pf[kt][0] = packh2(S[2 * kt][0],     S[2 * kt][1]);
            pf[kt][1] = packh2(S[2 * kt][2],     S[2 * kt][3]);
            pf[kt][2] = packh2(S[2 * kt + 1][0], S[2 * kt + 1][1]);
            pf[kt][3] = packh2(S[2 * kt + 1][2], S[2 * kt + 1][3]);
        }

        // ---- row sums of fp16 P via ones-vector mma (exact, no shfl) ----
        float cs[4] = {0.0f, 0.0f, 0.0f, 0.0f};
#pragma unroll
        for (int kt = 0; kt < 4; kt++)
            mma_f16(cs, pf[kt], onesb);
        l_i[0] = l_i[0] * alpha_s[0] + cs[0];
        l_i[1] = l_i[1] * alpha_s[1] + cs[2];

        // ---- O += P V (register P, single V term) ----
#pragma unroll
        for (int kt = 0; kt < 4; kt++) {
#pragma unroll
            for (int np = 0; np < 4; np++) {
                const int vrow = kt * 16 + (lane & 7) + 8 * ((lane >> 3) & 1);
                const int vcol = np * 16 + 8 * (lane >= 16);
                uint32_t vh_f[4];
                ldsm_x4t(vh_f, sptr(&Vh[vrow * AP + vcol]));
                mma_f16(O[np * 2],     pf[kt], vh_f);
                mma_f16(O[np * 2 + 1], pf[kt], vh_f + 2);
            }
        }
    }

    // ---- epilogue: normalize, write fp16 context [M, D] ----
    const int b = bh >> 4, h = bh & 15;
#pragma unroll
    for (int i = 0; i < 2; i++) {
        const float inv = 1.0f / l_i[i];
        const int s = q0 + wid * 16 + (lane >> 2) + i * 8;
        const size_t mrow = (size_t)(b * SEQ + s) * DM + h * HD;
#pragma unroll
        for (int nt = 0; nt < 8; nt++) {
            const int c = nt * 8 + (lane & 3) * 2;
            *(__half2*)&g_ch[mrow + c] =
                __floats2half2_rn(O[nt][2 * i] * inv, O[nt][2 * i + 1] * inv);
        }
    }
}

// ---------------------------------------------------------------------------
extern "C" void kernel_launch(void* const* d_in, const int* in_sizes, int n_in,
                              void* d_out, int out_size)
{
    (void)in_sizes; (void)n_in; (void)out_size;
    const float* x  = (const float*)d_in[0];
    const float* Wq = (const float*)d_in[1];
    const float* bq = (const float*)d_in[2];
    const float* Wk = (const float*)d_in[3];
    const float* bk = (const float*)d_in[4];
    const float* Wv = (const float*)d_in[5];
    const float* bv = (const float*)d_in[6];
    const float* Wo = (const float*)d_in[7];
    const float* bo = (const float*)d_in[8];
    float* out = (float*)d_out;

    split_all<<<NTHR / 256, 256>>>((const float4*)x, (const float4*)Wq,
                                   (const float4*)Wk, (const float4*)Wv,
                                   (const float4*)Wo);

    cudaFuncSetAttribute(hgemm<0>, cudaFuncAttributeMaxDynamicSharedMemorySize, GSMEM);
    cudaFuncSetAttribute(hgemm<1>, cudaFuncAttributeMaxDynamicSharedMemorySize, GSMEM);

    hgemm<0><<<dim3(8, 128, 3), 256, GSMEM>>>(bq, bk, bv, nullptr);

    cudaFuncSetAttribute(attn_kernel, cudaFuncAttributeMaxDynamicSharedMemorySize, ASMEM);
    attn_kernel<<<dim3(16, 64), 256, ASMEM>>>();

    hgemm<1><<<dim3(8, 128, 1), 256, GSMEM>>>(bo, nullptr, nullptr, out);
}

// round 17
// speedup vs baseline: 1.0303x; 1.0303x over previous
#include <cuda_runtime.h>
#include <cuda_fp16.h>
#include <stdint.h>

#define SEQ   2048
#define DM    1024
#define NH    16
#define HD    64
#define BATCH 4
#define MT    (BATCH * SEQ)   // 8192

// ---------------------------------------------------------------------------
// Scratch (static device globals — no allocations allowed)
// ---------------------------------------------------------------------------
__device__ __half g_xh[(size_t)MT * DM];
__device__ __half g_wqh[(size_t)DM * DM];
__device__ __half g_wkh[(size_t)DM * DM];
__device__ __half g_wvh[(size_t)DM * DM];
__device__ __half g_woh[(size_t)DM * DM];
__device__ __half g_qh[(size_t)MT * DM];     // [B,H,S,Dh]
__device__ __half g_kh[(size_t)MT * DM];     // [B,H,S,Dh]
__device__ __half g_vh[(size_t)MT * DM];     // [B,H,S,Dh]
__device__ __half g_ch[(size_t)MT * DM];     // context [M,D] (fp16)

// ---------------------------------------------------------------------------
// PTX helpers
// ---------------------------------------------------------------------------
__device__ __forceinline__ uint32_t sptr(const void* p) {
    return (uint32_t)__cvta_generic_to_shared(p);
}
__device__ __forceinline__ void ldsm_x4(uint32_t* r, uint32_t a) {
    asm volatile("ldmatrix.sync.aligned.m8n8.x4.shared.b16 {%0,%1,%2,%3}, [%4];"
                 : "=r"(r[0]), "=r"(r[1]), "=r"(r[2]), "=r"(r[3]) : "r"(a));
}
__device__ __forceinline__ void ldsm_x4t(uint32_t* r, uint32_t a) {
    asm volatile("ldmatrix.sync.aligned.m8n8.x4.trans.shared.b16 {%0,%1,%2,%3}, [%4];"
                 : "=r"(r[0]), "=r"(r[1]), "=r"(r[2]), "=r"(r[3]) : "r"(a));
}
__device__ __forceinline__ void mma_f16(float* c, const uint32_t* a, const uint32_t* b) {
    asm volatile(
        "mma.sync.aligned.m16n8k16.row.col.f32.f16.f16.f32 "
        "{%0,%1,%2,%3}, {%4,%5,%6,%7}, {%8,%9}, {%0,%1,%2,%3};"
        : "+f"(c[0]), "+f"(c[1]), "+f"(c[2]), "+f"(c[3])
        : "r"(a[0]), "r"(a[1]), "r"(a[2]), "r"(a[3]), "r"(b[0]), "r"(b[1]));
}
__device__ __forceinline__ void cpa16(uint32_t s, const void* g) {
    asm volatile("cp.async.cg.shared.global [%0], [%1], 16;" :: "r"(s), "l"(g));
}
#define CPA_COMMIT asm volatile("cp.async.commit_group;" ::: "memory")
#define CPA_WAIT2  asm volatile("cp.async.wait_group 2;" ::: "memory")
#define CPA_WAIT1  asm volatile("cp.async.wait_group 1;" ::: "memory")
#define CPA_WAIT0  asm volatile("cp.async.wait_group 0;" ::: "memory")

__device__ __forceinline__ float fexp2(float x) {
    float r;
    asm("ex2.approx.f32 %0, %1;" : "=f"(r) : "f"(x));
    return r;
}
__device__ __forceinline__ uint32_t packh2(float v0, float v1) {
    __half2 h = __floats2half2_rn(v0, v1);
    return *(uint32_t*)&h;
}

// ---------------------------------------------------------------------------
// Fused convert kernel: x and all 4 weights -> fp16.
// 4 independent float4 per thread (MLP=4) to cover LDG latency.
// ---------------------------------------------------------------------------
#define NX4  (MT * DM / 4)     // 2,097,152
#define NW4  (DM * DM / 4)     //   262,144
#define NTOT (NX4 + 4 * NW4)   // 3,145,728
#define NTHR (NTOT / 4)        //   786,432 threads, 4 slots each

__global__ __launch_bounds__(256) void split_all(
    const float4* __restrict__ x,  const float4* __restrict__ wq,
    const float4* __restrict__ wk, const float4* __restrict__ wv,
    const float4* __restrict__ wo)
{
    const int t = blockIdx.x * 256 + threadIdx.x;
#pragma unroll
    for (int k = 0; k < 4; k++) {
        const int i = t + k * NTHR;
        const float4* src;
        __half* H;
        int j;
        if (i < NX4) {
            src = x; H = g_xh; j = i;
        } else {
            j = i - NX4;
            const int which = j / NW4;
            j -= which * NW4;
            src = (which == 0) ? wq : (which == 1) ? wk : (which == 2) ? wv : wo;
            H   = (which == 0) ? g_wqh : (which == 1) ? g_wkh
                : (which == 2) ? g_wvh : g_woh;
        }
        float4 v = src[j];
        ((__half2*)(H + (size_t)j * 4))[0] = __floats2half2_rn(v.x, v.y);
        ((__half2*)(H + (size_t)j * 4))[1] = __floats2half2_rn(v.z, v.w);
    }
}

// ---------------------------------------------------------------------------
// Single-term fp16 GEMM (R14 configuration — measured optimum):
// C = A @ B^T + bias. k-chunk 64, 3-stage cp.async ring, occupancy 2.
// Block 128x128, 256 threads, warp tile 32x64 (mma:ldsm = 2.67).
// MODE 0 (QKV, z selects weight): A=x, fp16 out to [B,H,S,Dh]
// MODE 1 (Oproj): A=context, B=Wo, fp32 out
// ---------------------------------------------------------------------------
#define HP 72                       // smem pitch (halves) for 64-wide k-chunks
#define HT (128 * HP * 2)           // one tensor tile bytes (18432)
#define GSTAGE_B (2 * HT)           // Ah + Bh per stage (36864)
#define GSMEM    (3 * GSTAGE_B)     // 110592 (x2 CTAs = 221184 <= 227KB)

template <int MODE>
__global__ __launch_bounds__(256, 2) void hgemm(const float* b0, const float* b1,
                                                const float* b2, float* outf)
{
    extern __shared__ char smg[];
    const uint32_t su = sptr(smg);

    const int tid = threadIdx.x, wid = tid >> 5, lane = tid & 31;
    const int n0 = blockIdx.x * 128;
    const int m0 = blockIdx.y * 128;
    const int wm = (wid & 3) * 32;
    const int wn = (wid >> 2) * 64;

    const __half *gAh, *gBh;
    __half *Oh = nullptr;
    const float* bias;
    if (MODE == 0) {
        gAh = g_xh;
        const int which = blockIdx.z;
        if      (which == 0) { gBh = g_wqh; bias = b0; Oh = g_qh; }
        else if (which == 1) { gBh = g_wkh; bias = b1; Oh = g_kh; }
        else                 { gBh = g_wvh; bias = b2; Oh = g_vh; }
    } else {
        gAh = g_ch; gBh = g_woh; bias = b0;
    }

    float C[2][8][4];
#pragma unroll
    for (int a = 0; a < 2; a++)
#pragma unroll
        for (int b = 0; b < 8; b++)
#pragma unroll
            for (int c = 0; c < 4; c++) C[a][b][c] = 0.0f;

    // stage load: tensor = 128 rows x 64 halves; 1024 float4 slots; 4/thread
    auto load_stage = [&](int s, int k0) {
        const uint32_t sb = su + s * GSTAGE_B;
#pragma unroll
        for (int i = 0; i < 4; i++) {
            const int slot = i * 256 + tid;
            const int r = slot >> 3, c = (slot & 7) * 8;
            const uint32_t so = r * (HP * 2) + c * 2;
            cpa16(sb + so,      gAh + (size_t)(m0 + r) * DM + k0 + c);
            cpa16(sb + HT + so, gBh + (size_t)(n0 + r) * DM + k0 + c);
        }
    };

    load_stage(0, 0);
    CPA_COMMIT;
    load_stage(1, 64);
    CPA_COMMIT;

    for (int it = 0; it < 16; it++) {
        const int s = it % 3;
        if (it < 15) { CPA_WAIT1; } else { CPA_WAIT0; }
        __syncthreads();               // stage s ready; oldest stage free
        if (it + 2 < 16) {
            load_stage((it + 2) % 3, (it + 2) * 64);
            CPA_COMMIT;
        }

        const __half* sAh = (const __half*)(smg + s * GSTAGE_B);
        const __half* sBh = (const __half*)(smg + s * GSTAGE_B + HT);

#pragma unroll
        for (int ks = 0; ks < 4; ks++) {
            const int kk = ks * 16;
            uint32_t ah[2][4], bh[4][4];
#pragma unroll
            for (int mt = 0; mt < 2; mt++) {
                const int row = wm + mt * 16 + (lane & 15);
                const int col = kk + 8 * (lane >> 4);
                ldsm_x4(ah[mt], sptr(&sAh[row * HP + col]));
            }
#pragma unroll
            for (int np = 0; np < 4; np++) {
                const int row = wn + np * 16 + (lane & 7) + 8 * (lane >= 16);
                const int col = kk + 8 * ((lane >> 3) & 1);
                ldsm_x4(bh[np], sptr(&sBh[row * HP + col]));
            }
#pragma unroll
            for (int np = 0; np < 4; np++) {
                mma_f16(C[0][np * 2],     ah[0], bh[np]);
                mma_f16(C[0][np * 2 + 1], ah[0], bh[np] + 2);
                mma_f16(C[1][np * 2],     ah[1], bh[np]);
                mma_f16(C[1][np * 2 + 1], ah[1], bh[np] + 2);
            }
        }
    }

#pragma unroll
    for (int mt = 0; mt < 2; mt++)
#pragma unroll
        for (int nt = 0; nt < 8; nt++)
#pragma unroll
            for (int half = 0; half < 2; half++) {
                const int r = m0 + wm + mt * 16 + (lane >> 2) + half * 8;
                const int c = n0 + wn + nt * 8 + (lane & 3) * 2;
                const float v0 = C[mt][nt][half * 2 + 0] + __ldg(&bias[c]);
                const float v1 = C[mt][nt][half * 2 + 1] + __ldg(&bias[c + 1]);
                if (MODE == 0) {
                    const int b = r >> 11, s = r & 2047, h = c >> 6, d = c & 63;
                    const size_t off = ((((size_t)(b * NH + h)) * SEQ + s) << 6) + d;
                    *(__half2*)&Oh[off] = __floats2half2_rn(v0, v1);
                } else {
                    *(float2*)&outf[(size_t)r * DM + c] = make_float2(v0, v1);
                }
            }
}

// ---------------------------------------------------------------------------
// Flash attention (R14 configuration): single-term fp16 mma, register-P,
// fp32 softmax with folded scale + ones-mma row sums, 4-stage cp.async KV,
// one sync/iter, Q via cp.async.
// ---------------------------------------------------------------------------
#define AP 72
#define AQ_T      (128 * AP * 2)          // 18432 (Qh)
#define AKV_T     (64 * AP * 2)           // 9216
#define AKV_STAGE (2 * AKV_T)             // 18432 (Kh, Vh)
#define A_KV0     AQ_T                    // 18432
#define ASMEM     (A_KV0 + 4 * AKV_STAGE) // 92160  (x2 CTAs = 184320 <= 227KB)

__global__ __launch_bounds__(256, 2) void attn_kernel()
{
    extern __shared__ char sma[];
    const uint32_t su = sptr(sma);
    __half* Qh = (__half*)sma;

    const int tid = threadIdx.x, wid = tid >> 5, lane = tid & 31;
    const int bh = blockIdx.y;
    const int q0 = blockIdx.x * 128;
    const size_t base = (size_t)bh * SEQ * HD;

    const int kr = tid >> 3;            // 0..31
    const int kc = (tid & 7) * 8;

    auto load_kv = [&](int s, int s0) {
        const uint32_t sb = su + A_KV0 + s * AKV_STAGE;
#pragma unroll
        for (int i = 0; i < 2; i++) {
            const int r = kr + i * 32;
            const size_t g = base + (size_t)(s0 + r) * HD + kc;
            const uint32_t so = r * (AP * 2) + kc * 2;
            cpa16(sb + so,           g_kh + g);
            cpa16(sb + AKV_T + so,   g_vh + g);
        }
    };

    // Q tile (128x64) via cp.async, grouped with KV stage 0
#pragma unroll
    for (int i = 0; i < 4; i++) {
        const int slot = i * 256 + tid;
        const int r = slot >> 3, c = (slot & 7) * 8;
        cpa16(su + r * (AP * 2) + c * 2,
              g_qh + base + (size_t)(q0 + r) * HD + c);
    }
    load_kv(0, 0);
    CPA_COMMIT;
    load_kv(1, 64);
    CPA_COMMIT;
    load_kv(2, 128);
    CPA_COMMIT;

    // wait for Q + stage 0 (2 groups still in flight), then hoist Q frags
    CPA_WAIT2;
    __syncthreads();

    uint32_t qh_f[4][4];
#pragma unroll
    for (int kt = 0; kt < 4; kt++) {
        const int row = wid * 16 + (lane & 15);
        const int col = kt * 16 + 8 * (lane >> 4);
        ldsm_x4(qh_f[kt], sptr(&Qh[row * AP + col]));
    }

    float m_i[2] = {-1e30f, -1e30f}, l_i[2] = {0.0f, 0.0f};
    float O[8][4];
#pragma unroll
    for (int a = 0; a < 8; a++)
#pragma unroll
        for (int b = 0; b < 4; b++) O[a][b] = 0.0f;

    const float SCALE = 0.125f * 1.44269504089f;   // 1/sqrt(64) * log2(e)
    const uint32_t ONES2 = 0x3C003C00u;            // half2 {1, 1}
    const uint32_t onesb[2] = {ONES2, ONES2};
    const int NIT = SEQ / 64;                      // 32

    for (int it = 0; it < NIT; it++) {
        const int s = it & 3;
        if (it > 0) {
            if (it < NIT - 1) { CPA_WAIT2; } else { CPA_WAIT0; }
            __syncthreads();           // stage s ready; stage (it+3)&3 free
        }
        if (it + 3 < NIT) {
            load_kv((it + 3) & 3, (it + 3) * 64);
            CPA_COMMIT;
        }

        const __half* Kh = (const __half*)(sma + A_KV0 + s * AKV_STAGE);
        const __half* Vh = (const __half*)(sma + A_KV0 + s * AKV_STAGE + AKV_T);

        // ---- S = Q K^T (single term) ----
        float S[8][4];
#pragma unroll
        for (int a = 0; a < 8; a++)
#pragma unroll
            for (int b = 0; b < 4; b++) S[a][b] = 0.0f;

#pragma unroll
        for (int kt = 0; kt < 4; kt++) {
#pragma unroll
            for (int np = 0; np < 4; np++) {
                const int row = np * 16 + (lane & 7) + 8 * (lane >= 16);
                const int col = kt * 16 + 8 * ((lane >> 3) & 1);
                uint32_t kh_f[4];
                ldsm_x4(kh_f, sptr(&Kh[row * AP + col]));
                mma_f16(S[np * 2],     qh_f[kt], kh_f);
                mma_f16(S[np * 2 + 1], qh_f[kt], kh_f + 2);
            }
        }

        // ---- online softmax: raw-unit max, scale folded into exp FFMA ----
        float alpha_s[2];
#pragma unroll
        for (int i = 0; i < 2; i++) {
            float rowmax = -1e30f;
#pragma unroll
            for (int nt = 0; nt < 8; nt++)
                rowmax = fmaxf(rowmax, fmaxf(S[nt][2 * i], S[nt][2 * i + 1]));
            rowmax = fmaxf(rowmax, __shfl_xor_sync(0xffffffffu, rowmax, 1));
            rowmax = fmaxf(rowmax, __shfl_xor_sync(0xffffffffu, rowmax, 2));
            const float mnew  = fmaxf(m_i[i], rowmax);
            const float alpha = fexp2((m_i[i] - mnew) * SCALE);
            alpha_s[i] = alpha;
            m_i[i] = mnew;
            const float nms = -mnew * SCALE;
#pragma unroll
            for (int nt = 0; nt < 8; nt++) {
                S[nt][2 * i]     = fexp2(fmaf(S[nt][2 * i],     SCALE, nms));
                S[nt][2 * i + 1] = fexp2(fmaf(S[nt][2 * i + 1], SCALE, nms));
                O[nt][2 * i]     *= alpha;
                O[nt][2 * i + 1] *= alpha;
            }
        }

        // ---- pack P fragments from S registers (C-layout == A-layout) ----
        uint32_t pf[4][4];
#pragma unroll
        for (int kt = 0; kt < 4; kt++) {
            pf[kt][0] = packh2(S[2 * kt][0],     S[2 * kt][1]);
            pf[kt][1] = packh2(S[2 * kt][2],     S[2 * kt][3]);
            pf[kt][2] = packh2(S[2 * kt + 1][0], S[2 * kt + 1][1]);
            pf[kt][3] = packh2(S[2 * kt + 1][2], S[2 * kt + 1][3]);
        }

        // ---- row sums of fp16 P via ones-vector mma (exact, no shfl) ----
        float cs[4] = {0.0f, 0.0f, 0.0f, 0.0f};
#pragma unroll
        for (int kt = 0; kt < 4; kt++)
            mma_f16(cs, pf[kt], onesb);
        l_i[0] = l_i[0] * alpha_s[0] + cs[0];
        l_i[1] = l_i[1] * alpha_s[1] + cs[2];

        // ---- O += P V (register P, single V term) ----
#pragma unroll
        for (int kt = 0; kt < 4; kt++) {
#pragma unroll
            for (int np = 0; np < 4; np++) {
                const int vrow = kt * 16 + (lane & 7) + 8 * ((lane >> 3) & 1);
                const int vcol = np * 16 + 8 * (lane >= 16);
                uint32_t vh_f[4];
                ldsm_x4t(vh_f, sptr(&Vh[vrow * AP + vcol]));
                mma_f16(O[np * 2],     pf[kt], vh_f);
                mma_f16(O[np * 2 + 1], pf[kt], vh_f + 2);
            }
        }
    }

    // ---- epilogue: normalize, write fp16 context [M, D] ----
    const int b = bh >> 4, h = bh & 15;
#pragma unroll
    for (int i = 0; i < 2; i++) {
        const float inv = 1.0f / l_i[i];
        const int s = q0 + wid * 16 + (lane >> 2) + i * 8;
        const size_t mrow = (size_t)(b * SEQ + s) * DM + h * HD;
#pragma unroll
        for (int nt = 0; nt < 8; nt++) {
            const int c = nt * 8 + (lane & 3) * 2;
            *(__half2*)&g_ch[mrow + c] =
                __floats2half2_rn(O[nt][2 * i] * inv, O[nt][2 * i + 1] * inv);
        }
    }
}

// ---------------------------------------------------------------------------
extern "C" void kernel_launch(void* const* d_in, const int* in_sizes, int n_in,
                              void* d_out, int out_size)
{
    (void)in_sizes; (void)n_in; (void)out_size;
    const float* x  = (const float*)d_in[0];
    const float* Wq = (const float*)d_in[1];
    const float* bq = (const float*)d_in[2];
    const float* Wk = (const float*)d_in[3];
    const float* bk = (const float*)d_in[4];
    const float* Wv = (const float*)d_in[5];
    const float* bv = (const float*)d_in[6];
    const float* Wo = (const float*)d_in[7];
    const float* bo = (const float*)d_in[8];
    float* out = (float*)d_out;

    split_all<<<NTHR / 256, 256>>>((const float4*)x, (const float4*)Wq,
                                   (const float4*)Wk, (const float4*)Wv,
                                   (const float4*)Wo);

    cudaFuncSetAttribute(hgemm<0>, cudaFuncAttributeMaxDynamicSharedMemorySize, GSMEM);
    cudaFuncSetAttribute(hgemm<1>, cudaFuncAttributeMaxDynamicSharedMemorySize, GSMEM);

    hgemm<0><<<dim3(8, 64, 3), 256, GSMEM>>>(bq, bk, bv, nullptr);

    cudaFuncSetAttribute(attn_kernel, cudaFuncAttributeMaxDynamicSharedMemorySize, ASMEM);
    attn_kernel<<<dim3(16, 64), 256, ASMEM>>>();

    hgemm<1><<<dim3(8, 64, 1), 256, GSMEM>>>(bo, nullptr, nullptr, out);
}